// round 7
// baseline (speedup 1.0000x reference)
#include <cuda_runtime.h>
#include <cstdint>

// Quantizer: per-row symmetric int4 quant + nibble pack. x: [8192, 4096] fp32.
// Output = concat(packed, scales) upcast to fp32:
//   out[0 .. N*2048)       fp32 value of each packed signed byte
//   out[N*2048 .. +N)      fp32 per-row scale (absmax / 7)
//
// R6: TWO rows per CTA, fused reduction (one barrier pair per 2 rows),
// 8 front-batched LDG.128 per thread; default-cached loads (preserve L2
// replay residency), streaming stores.

#define H 4096
#define HP (H / 2)
#define THREADS 256

__device__ __forceinline__ float pack2(float a, float b, float inv) {
    int q0 = min(max(__float2int_rn(a * inv), -8), 7);
    int q1 = min(max(__float2int_rn(b * inv), -8), 7);
    return (float)((int8_t)(((q1 & 0xF) << 4) | (q0 & 0xF)));
}

__device__ __forceinline__ float amax4(float4 v) {
    return fmaxf(fmaxf(fabsf(v.x), fabsf(v.y)), fmaxf(fabsf(v.z), fabsf(v.w)));
}

__global__ __launch_bounds__(THREADS)
void quant_pack_kernel(const float* __restrict__ x,
                       float* __restrict__ out_packed,
                       float* __restrict__ out_scales)
{
    const int t = threadIdx.x;
    const int rowA = blockIdx.x * 2;
    const int rowB = rowA + 1;

    const float4* __restrict__ xA = reinterpret_cast<const float4*>(x + (size_t)rowA * H);
    const float4* __restrict__ xB = reinterpret_cast<const float4*>(x + (size_t)rowB * H);

    // Front-batch all 8 LDG.128 (both rows) — sustained MLP across the
    // reduce/store tail of the previous wave.
    float4 a0 = xA[2 * t];
    float4 a1 = xA[2 * t + 1];
    float4 a2 = xA[512 + 2 * t];
    float4 a3 = xA[512 + 2 * t + 1];
    float4 b0 = xB[2 * t];
    float4 b1 = xB[2 * t + 1];
    float4 b2 = xB[512 + 2 * t];
    float4 b3 = xB[512 + 2 * t + 1];

    float mA = fmaxf(fmaxf(amax4(a0), amax4(a1)), fmaxf(amax4(a2), amax4(a3)));
    float mB = fmaxf(fmaxf(amax4(b0), amax4(b1)), fmaxf(amax4(b2), amax4(b3)));

    // Warp reduce both rows (interleaved shuffles).
#pragma unroll
    for (int o = 16; o > 0; o >>= 1) {
        mA = fmaxf(mA, __shfl_xor_sync(0xffffffffu, mA, o));
        mB = fmaxf(mB, __shfl_xor_sync(0xffffffffu, mB, o));
    }

    __shared__ float warpmaxA[THREADS / 32];
    __shared__ float warpmaxB[THREADS / 32];
    __shared__ float s_invA, s_invB;
    const int wid = t >> 5;
    const int lane = t & 31;
    if (lane == 0) { warpmaxA[wid] = mA; warpmaxB[wid] = mB; }
    __syncthreads();

    // Warp 0 finalizes row A, warp 1 finalizes row B — in parallel.
    if (wid < 2) {
        const float* wm = (wid == 0) ? warpmaxA : warpmaxB;
        float mm = (lane < THREADS / 32) ? wm[lane] : 0.0f;
#pragma unroll
        for (int o = 4; o > 0; o >>= 1)
            mm = fmaxf(mm, __shfl_xor_sync(0xffffffffu, mm, o));
        if (lane == 0) {
            const float sc = mm / 7.0f;            // exact divide, once per row
            out_scales[(wid == 0) ? rowA : rowB] = sc;
            if (wid == 0) s_invA = 1.0f / sc;      // exact reciprocal
            else          s_invB = 1.0f / sc;
        }
    }
    __syncthreads();
    const float invA = s_invA;
    const float invB = s_invB;

    // 4 streaming STG.128 per thread.
    float4* __restrict__ oA = reinterpret_cast<float4*>(out_packed + (size_t)rowA * HP);
    float4* __restrict__ oB = reinterpret_cast<float4*>(out_packed + (size_t)rowB * HP);

    float4 p;
    p.x = pack2(a0.x, a0.y, invA); p.y = pack2(a0.z, a0.w, invA);
    p.z = pack2(a1.x, a1.y, invA); p.w = pack2(a1.z, a1.w, invA);
    __stcs(&oA[t], p);
    p.x = pack2(a2.x, a2.y, invA); p.y = pack2(a2.z, a2.w, invA);
    p.z = pack2(a3.x, a3.y, invA); p.w = pack2(a3.z, a3.w, invA);
    __stcs(&oA[256 + t], p);
    p.x = pack2(b0.x, b0.y, invB); p.y = pack2(b0.z, b0.w, invB);
    p.z = pack2(b1.x, b1.y, invB); p.w = pack2(b1.z, b1.w, invB);
    __stcs(&oB[t], p);
    p.x = pack2(b2.x, b2.y, invB); p.y = pack2(b2.z, b2.w, invB);
    p.z = pack2(b3.x, b3.y, invB); p.w = pack2(b3.z, b3.w, invB);
    __stcs(&oB[256 + t], p);
}

extern "C" void kernel_launch(void* const* d_in, const int* in_sizes, int n_in,
                              void* d_out, int out_size)
{
    const float* x = (const float*)d_in[0];
    const int N = in_sizes[0] / H;                   // 8192 rows

    float* out_packed = (float*)d_out;
    float* out_scales = (float*)d_out + (size_t)N * HP;

    quant_pack_kernel<<<N / 2, THREADS>>>(x, out_packed, out_scales);
}

// round 9
// speedup vs baseline: 1.0185x; 1.0185x over previous
#include <cuda_runtime.h>
#include <cstdint>

// Quantizer: per-row symmetric int4 quant + nibble pack. x: [8192, 4096] fp32.
// Output = concat(packed, scales) upcast to fp32:
//   out[0 .. N*2048)       fp32 value of each packed signed byte
//   out[N*2048 .. +N)      fp32 per-row scale (absmax / 7)
//
// (Resubmission: Round-8 bench was an infra failure — container never ran it.)
// R7: best structure (R5: 1 row/CTA, 256T, paired mapping, 2x STG.128, occ 8).
// New: __stwt write-through stores (no L2 dirty-line allocation) so the 128MB
// input can stay L2-resident across graph replays (L2=126MB); default-cached
// loads to maximize that residency.

#define H 4096
#define HP (H / 2)
#define THREADS 256
// thread t owns input float4s {2t, 2t+1, 512+2t, 512+2t+1} (16 floats),
// emitting output float4s {t, 256+t} (8 packed-byte floats).

__device__ __forceinline__ float pack2(float a, float b, float inv) {
    int q0 = min(max(__float2int_rn(a * inv), -8), 7);
    int q1 = min(max(__float2int_rn(b * inv), -8), 7);
    return (float)((int8_t)(((q1 & 0xF) << 4) | (q0 & 0xF)));
}

__device__ __forceinline__ float amax4(float4 v) {
    return fmaxf(fmaxf(fabsf(v.x), fabsf(v.y)), fmaxf(fabsf(v.z), fabsf(v.w)));
}

__global__ __launch_bounds__(THREADS, 8)
void quant_pack_kernel(const float* __restrict__ x,
                       float* __restrict__ out_packed,
                       float* __restrict__ out_scales)
{
    const int t = threadIdx.x;
    const int row = blockIdx.x;
    const float4* __restrict__ xrow =
        reinterpret_cast<const float4*>(x + (size_t)row * H);

    // Default-cached loads (keep x resident in L2 across replays).
    float4 v0 = xrow[2 * t];
    float4 v1 = xrow[2 * t + 1];
    float4 v2 = xrow[512 + 2 * t];
    float4 v3 = xrow[512 + 2 * t + 1];

    float m = fmaxf(fmaxf(amax4(v0), amax4(v1)), fmaxf(amax4(v2), amax4(v3)));

    // Warp absmax, then cross-warp via shared + warp-0 shuffle reduce.
#pragma unroll
    for (int o = 16; o > 0; o >>= 1)
        m = fmaxf(m, __shfl_xor_sync(0xffffffffu, m, o));

    __shared__ float warpmax[THREADS / 32];
    __shared__ float s_inv;
    if ((t & 31) == 0) warpmax[t >> 5] = m;
    __syncthreads();
    if (t < 32) {
        float mm = (t < THREADS / 32) ? warpmax[t] : 0.0f;
#pragma unroll
        for (int o = 4; o > 0; o >>= 1)
            mm = fmaxf(mm, __shfl_xor_sync(0xffffffffu, mm, o));
        if (t == 0) {
            const float sc = mm / 7.0f;   // exact divide, once per row
            __stwt(&out_scales[row], sc); // write-through, don't pollute L2
            s_inv = 1.0f / sc;            // exact reciprocal, once per row
        }
    }
    __syncthreads();
    const float inv = s_inv;

    // Two write-through STG.128 per thread — no L2 allocation, so the
    // output stream doesn't evict the (nearly L2-sized) input.
    float4* __restrict__ orow =
        reinterpret_cast<float4*>(out_packed + (size_t)row * HP);
    float4 o0, o1;
    o0.x = pack2(v0.x, v0.y, inv);
    o0.y = pack2(v0.z, v0.w, inv);
    o0.z = pack2(v1.x, v1.y, inv);
    o0.w = pack2(v1.z, v1.w, inv);
    o1.x = pack2(v2.x, v2.y, inv);
    o1.y = pack2(v2.z, v2.w, inv);
    o1.z = pack2(v3.x, v3.y, inv);
    o1.w = pack2(v3.z, v3.w, inv);
    __stwt(&orow[t], o0);
    __stwt(&orow[256 + t], o1);
}

extern "C" void kernel_launch(void* const* d_in, const int* in_sizes, int n_in,
                              void* d_out, int out_size)
{
    const float* x = (const float*)d_in[0];
    const int N = in_sizes[0] / H;                   // 8192 rows

    float* out_packed = (float*)d_out;
    float* out_scales = (float*)d_out + (size_t)N * HP;

    quant_pack_kernel<<<N, THREADS>>>(x, out_packed, out_scales);
}